// round 11
// baseline (speedup 1.0000x reference)
#include <cuda_runtime.h>
#include <cuda_bf16.h>
#include <cstdint>
#include <cstddef>

// ---------------- problem constants ----------------
#define BSZ   4
#define SEQ   128
#define TOK   (BSZ*SEQ)        // 512
#define DM    256
#define FF    2048
#define PP    224
#define PED   512
#define PEROW (PP*PED)         // 114688

// output region sizes (floats)
#define SZ_AHID (4LL*192*16*4096)
#define SZ_AINT (4LL*32*16*11008)
#define SZ_BHID (4LL*96*4096*16)
#define SZ_BKV  (4LL*64*1024*16)
#define OFF_AINT (SZ_AHID)
#define OFF_BHID (SZ_AHID+SZ_AINT)
#define OFF_BKV  (OFF_BHID+SZ_BHID)
#define OFF_BINT (OFF_BKV+SZ_BKV)

// ---------------- scratch ----------------
#define S_X     0
#define S_QKV   (S_X    + TOK*DM)
#define S_ATTN  (S_QKV  + TOK*3*DM)
#define S_FF1   (S_ATTN + TOK*DM)
#define S_POOL  (S_FF1  + TOK*FF)
#define S_PE    (S_POOL + BSZ*DM)
#define S_DECHA (S_PE   + BSZ*PEROW)
#define S_DECHB (S_DECHA + 896*DM)
#define S_AB    (S_DECHB + 896*DM)
#define S_BB    (S_AB   + 896*1024)
#define S_PART  (S_BB   + 896*1024)
#define S_TOTAL (S_PART + 4*TOK*DM)

__device__ float g_scratch[S_TOTAL];

// ---------------- PDL helpers ----------------
__device__ __forceinline__ void gdc_wait()   { asm volatile("griddepcontrol.wait;" ::: "memory"); }
__device__ __forceinline__ void gdc_launch() { asm volatile("griddepcontrol.launch_dependents;" ::: "memory"); }

// ---------------- math helpers ----------------
__device__ __forceinline__ unsigned f2tf(float x) {
    unsigned u; asm("cvt.rna.tf32.f32 %0, %1;" : "=r"(u) : "f"(x)); return u;
}
__device__ __forceinline__ void mma_tf32(float* d, const unsigned* a, const unsigned* b) {
    asm volatile("mma.sync.aligned.m16n8k8.row.col.f32.tf32.tf32.f32 "
        "{%0,%1,%2,%3}, {%4,%5,%6,%7}, {%8,%9}, {%0,%1,%2,%3};\n"
        : "+f"(d[0]), "+f"(d[1]), "+f"(d[2]), "+f"(d[3])
        : "r"(a[0]), "r"(a[1]), "r"(a[2]), "r"(a[3]), "r"(b[0]), "r"(b[1]));
}
__device__ __forceinline__ void cp16(float* smem_dst, const float* gsrc) {
    unsigned s = (unsigned)__cvta_generic_to_shared(smem_dst);
    asm volatile("cp.async.ca.shared.global [%0], [%1], 16;" :: "r"(s), "l"(gsrc));
}
__device__ __forceinline__ void cp_commit() { asm volatile("cp.async.commit_group;"); }
template<int N>
__device__ __forceinline__ void cp_wait() { asm volatile("cp.async.wait_group %0;" :: "n"(N)); }

// ---------------- kernels ----------------

// C[m,n] = epi( sum_k X[m,k]*W[n,k] + bias[n] ), tf32 tensor cores.
// BM=BN=32, BK=32, 128 threads (4 warps, 16x16 warp tile), 4-stage cp.async pipeline.
// W prefetched pre-gdc_wait; gids!=null gathers X rows from Etab[gids[row]].
#define SK 36
#define STG 4
template<int EPI, int BATCH>
__global__ __launch_bounds__(128) void gemm32(
        const float* __restrict__ X, const float* __restrict__ W,
        const float* __restrict__ bias, float* __restrict__ C,
        float* __restrict__ Cpart,
        const float* __restrict__ X2, const float* __restrict__ W2,
        const float* __restrict__ bias2, float* __restrict__ C2,
        const int* __restrict__ gids, const float* __restrict__ Etab,
        int M, int N, int K) {
    __shared__ float Xs[STG][32][SK];
    __shared__ float Ws[STG][32][SK];
    int tid = threadIdx.x;
    int lane = tid & 31, wid = tid >> 5;
    int wm = wid & 1, wn = wid >> 1;
    int r = lane >> 2, cq = lane & 3;
    int m0 = blockIdx.y * 32, n0 = blockIdx.x * 32;
    int kbeg, nk;
    if (BATCH) {
        if (blockIdx.z) { X = X2; W = W2; bias = bias2; C = C2; }
        kbeg = 0; nk = K >> 5;
    } else {
        int kchunk = K / gridDim.z;
        kbeg = blockIdx.z * kchunk;
        nk = kchunk >> 5;
    }

    int row2 = tid >> 3;              // 0..15
    int colq = (tid & 7) * 4;         // 0..28
    size_t rstep = (size_t)16 * K;
    const float *xrow0, *xrow1;
    if (gids) {
        xrow0 = Etab + (size_t)gids[m0 + row2] * 256 + colq;
        xrow1 = Etab + (size_t)gids[m0 + row2 + 16] * 256 + colq;
    } else {
        xrow0 = X + (size_t)(m0 + row2) * K + kbeg + colq;
        xrow1 = xrow0 + rstep;
    }
    const float* wg = W + (size_t)(n0 + row2) * K + kbeg + colq;

    #pragma unroll
    for (int s = 0; s < STG-1; ++s) {
        if (s < nk) {
            const float* wp = wg + s*32;
            cp16(&Ws[s][row2][colq],    wp);
            cp16(&Ws[s][row2+16][colq], wp + rstep);
        }
    }
    cp_commit();                       // G0 (weights, pre-wait)

    gdc_wait();

    #pragma unroll
    for (int s = 0; s < STG-1; ++s) {  // G1..G3 = X stages
        if (s < nk) {
            cp16(&Xs[s][row2][colq],    xrow0 + s*32);
            cp16(&Xs[s][row2+16][colq], xrow1 + s*32);
        }
        cp_commit();
    }

    float acc[2][4] = {};

    for (int kt = 0; kt < nk; ++kt) {
        int buf = kt & (STG-1);
        cp_wait<STG-2>();
        __syncthreads();
        {
            int ks2 = kt + STG - 1;
            if (ks2 < nk) {
                int b2 = ks2 & (STG-1);
                cp16(&Xs[b2][row2][colq],    xrow0 + ks2*32);
                cp16(&Xs[b2][row2+16][colq], xrow1 + ks2*32);
                const float* wp = wg + ks2*32;
                cp16(&Ws[b2][row2][colq],    wp);
                cp16(&Ws[b2][row2+16][colq], wp + rstep);
            }
            cp_commit();
        }
        #pragma unroll
        for (int ks = 0; ks < 4; ++ks) {
            unsigned af[4];
            int mr = wm*16 + r;
            af[0] = f2tf(Xs[buf][mr][ks*8 + cq]);
            af[1] = f2tf(Xs[buf][mr + 8][ks*8 + cq]);
            af[2] = f2tf(Xs[buf][mr][ks*8 + cq + 4]);
            af[3] = f2tf(Xs[buf][mr + 8][ks*8 + cq + 4]);
            #pragma unroll
            for (int nt = 0; nt < 2; ++nt) {
                unsigned bf[2];
                int nr = wn*16 + nt*8 + r;
                bf[0] = f2tf(Ws[buf][nr][ks*8 + cq]);
                bf[1] = f2tf(Ws[buf][nr][ks*8 + cq + 4]);
                mma_tf32(acc[nt], af, bf);
            }
        }
    }

    int m = m0 + wm*16 + r;
    if (!BATCH && gridDim.z > 1) {
        float* P = Cpart + (size_t)blockIdx.z * M * N;
        #pragma unroll
        for (int nt = 0; nt < 2; ++nt) {
            int n = n0 + wn*16 + nt*8 + cq*2;
            #pragma unroll
            for (int half = 0; half < 2; ++half)
                *reinterpret_cast<float2*>(&P[(size_t)(m + half*8)*N + n]) =
                    make_float2(acc[nt][half*2], acc[nt][half*2+1]);
        }
    } else {
        #pragma unroll
        for (int nt = 0; nt < 2; ++nt) {
            int n = n0 + wn*16 + nt*8 + cq*2;
            #pragma unroll
            for (int half = 0; half < 2; ++half) {
                float v0 = acc[nt][half*2+0] + bias[n];
                float v1 = acc[nt][half*2+1] + bias[n+1];
                if (EPI == 1) { v0 = fmaxf(v0, 0.f); v1 = fmaxf(v1, 0.f); }
                if (EPI == 2) {
                    v0 = 0.5f*v0*(1.f + erff(v0*0.70710678118654752f));
                    v1 = 0.5f*v1*(1.f + erff(v1*0.70710678118654752f));
                }
                *reinterpret_cast<float2*>(&C[(size_t)(m + half*8)*N + n]) = make_float2(v0, v1);
            }
        }
    }
    gdc_launch();
}

// split-K reduce + bias + residual + LayerNorm, warp-per-row. grid 64 x 256 thr.
// gids!=null: residual from Etab[gids[row]] (layer-0 fold).
// zbuf!=null: blocks 0..3 also zero zbuf[1024] (pooled pre-zero, runs stages earlier).
// poolacc!=null: after LN, atomicAdd x*mask into poolacc (final-layer pooling fold).
__global__ __launch_bounds__(256) void ksplit_ln(
        const float* __restrict__ P, const float* __restrict__ bias,
        float* __restrict__ x, const float* __restrict__ g,
        const float* __restrict__ b, int parts,
        const int* __restrict__ gids, const float* __restrict__ Etab,
        const int* __restrict__ mask, float* __restrict__ poolacc,
        float* __restrict__ zbuf) {
    int wid = threadIdx.x >> 5, lane = threadIdx.x & 31;
    int row = blockIdx.x * 8 + wid;
    size_t base = (size_t)row * 256;
    const float* rsrc = gids ? (Etab + (size_t)gids[row] * 256) : (x + base);
    gdc_wait();
    if (zbuf && blockIdx.x < 4) zbuf[blockIdx.x * 256 + threadIdx.x] = 0.f;
    float h[8]; float s1 = 0.f, s2 = 0.f;
    #pragma unroll
    for (int i = 0; i < 8; ++i) {
        int c = lane + i*32;
        float s = bias[c];
        for (int p = 0; p < parts; ++p) s += P[(size_t)p*TOK*DM + base + c];
        float hv = rsrc[c] + s;
        h[i] = hv; s1 += hv; s2 += hv*hv;
    }
    #pragma unroll
    for (int off = 16; off > 0; off >>= 1) {
        s1 += __shfl_xor_sync(0xFFFFFFFFu, s1, off);
        s2 += __shfl_xor_sync(0xFFFFFFFFu, s2, off);
    }
    float mean = s1 * (1.f/256.f);
    float var = s2 * (1.f/256.f) - mean*mean;
    float inv = rsqrtf(var + 1e-5f);
    float am = poolacc ? (float)mask[row] : 0.f;
    int bb = row >> 7;
    #pragma unroll
    for (int i = 0; i < 8; ++i) {
        int c = lane + i*32;
        float v = (h[i] - mean) * inv * g[c] + b[c];
        x[base + c] = v;
        if (poolacc) atomicAdd(&poolacc[bb*256 + c], v * am);
    }
    gdc_launch();
}

// Fused attention: block = (q-chunk of 16, b*4+h). 256 threads, grid (8,16).
#define AQ_OFF 0
#define AK_OFF (16*68)
#define AV_OFF (AK_OFF + 128*68)
#define AP_OFF (AV_OFF + 128*68)
#define ATT_SMEM ((AP_OFF + 16*129)*4)
__global__ void attn_fused(const float* __restrict__ qkv, const int* __restrict__ mask,
                           float* __restrict__ o) {
    extern __shared__ float sm[];
    int tid = threadIdx.x;
    int qc = blockIdx.x;
    int bh = blockIdx.y;
    int b = bh >> 2, h = bh & 3;

    gdc_wait();
    const float4* src = reinterpret_cast<const float4*>(qkv);
    {
        int row = tid >> 4, d4 = tid & 15;
        float4 v = src[((size_t)(b*128 + qc*16 + row)*768 + h*64) / 4 + d4];
        *reinterpret_cast<float4*>(&sm[AQ_OFF + row*68 + d4*4]) = v;
    }
    #pragma unroll
    for (int it = 0; it < 8; ++it) {
        int e = it*256 + tid;
        int row = e >> 4, d4 = e & 15;
        float4 k = src[((size_t)(b*128 + row)*768 + 256 + h*64) / 4 + d4];
        float4 v = src[((size_t)(b*128 + row)*768 + 512 + h*64) / 4 + d4];
        *reinterpret_cast<float4*>(&sm[AK_OFF + row*68 + d4*4]) = k;
        *reinterpret_cast<float4*>(&sm[AV_OFF + row*68 + d4*4]) = v;
    }
    __syncthreads();

    int q = tid >> 4;
    int kb = tid & 15;
    float s[8];
    #pragma unroll
    for (int i = 0; i < 8; ++i) {
        int k = kb + 16*i;
        const float4* qp = reinterpret_cast<const float4*>(&sm[AQ_OFF + q*68]);
        const float4* kp = reinterpret_cast<const float4*>(&sm[AK_OFF + k*68]);
        float acc = 0.f;
        #pragma unroll
        for (int d4 = 0; d4 < 16; ++d4) {
            float4 a = qp[d4], c = kp[d4];
            acc += a.x*c.x + a.y*c.y + a.z*c.z + a.w*c.w;
        }
        acc *= 0.125f;
        if (mask[b*128 + k] == 0) acc = -1e9f;
        s[i] = acc;
    }
    float mx = s[0];
    #pragma unroll
    for (int i = 1; i < 8; ++i) mx = fmaxf(mx, s[i]);
    #pragma unroll
    for (int off = 1; off < 16; off <<= 1)
        mx = fmaxf(mx, __shfl_xor_sync(0xFFFFFFFFu, mx, off));
    float sum = 0.f;
    #pragma unroll
    for (int i = 0; i < 8; ++i) { s[i] = __expf(s[i] - mx); sum += s[i]; }
    #pragma unroll
    for (int off = 1; off < 16; off <<= 1)
        sum += __shfl_xor_sync(0xFFFFFFFFu, sum, off);
    float inv = 1.f / sum;
    #pragma unroll
    for (int i = 0; i < 8; ++i)
        sm[AP_OFF + q*129 + kb + 16*i] = s[i] * inv;
    __syncthreads();

    int dg = tid & 15;
    float4 acc4 = {0.f, 0.f, 0.f, 0.f};
    const float* Pr = &sm[AP_OFF + q*129];
    #pragma unroll 4
    for (int k = 0; k < 128; ++k) {
        float p = Pr[k];
        float4 v = *reinterpret_cast<const float4*>(&sm[AV_OFF + k*68 + dg*4]);
        acc4.x += p*v.x; acc4.y += p*v.y; acc4.z += p*v.z; acc4.w += p*v.w;
    }
    size_t orow = (size_t)(b*128 + qc*16 + q)*256 + h*64 + dg*4;
    *reinterpret_cast<float4*>(&o[orow]) = acc4;
    gdc_launch();
}

// pe: warp-per-row over 114688 rows; normalizes pooled by mask count itself.
__global__ void pe_kernel(const float* __restrict__ pooled, const int* __restrict__ mask,
                          const float* __restrict__ W, const float* __restrict__ bias,
                          float* __restrict__ pe) {
    __shared__ float sp[1024];
    __shared__ float invden[4];
    int t = threadIdx.x;
    int warp = t >> 5, lane = t & 31;
    int j = blockIdx.x * 8 + warp;
    const float4* w4 = reinterpret_cast<const float4*>(W + (size_t)j * 256);
    float4 w0 = w4[lane];
    float4 w1 = w4[lane + 32];
    // mask is a kernel input: denominators computable pre-wait
    if (t < 4) {
        int s = 0;
        for (int i = 0; i < 128; ++i) s += mask[t*128 + i];
        invden[t] = 1.f / fmaxf((float)s, 1.f);
    }
    gdc_wait();
    #pragma unroll
    for (int i = 0; i < 4; ++i) sp[t + i*256] = pooled[t + i*256];
    __syncthreads();
    int k0 = lane * 4, k1 = (lane + 32) * 4;
    float acc[4];
    #pragma unroll
    for (int b = 0; b < 4; ++b) {
        const float* p = &sp[b*256];
        acc[b] = w0.x*p[k0] + w0.y*p[k0+1] + w0.z*p[k0+2] + w0.w*p[k0+3]
               + w1.x*p[k1] + w1.y*p[k1+1] + w1.z*p[k1+2] + w1.w*p[k1+3];
    }
    #pragma unroll
    for (int b = 0; b < 4; ++b)
        #pragma unroll
        for (int off = 16; off > 0; off >>= 1)
            acc[b] += __shfl_xor_sync(0xFFFFFFFFu, acc[b], off);
    if (lane < 4) pe[(size_t)lane * PEROW + j] = acc[lane] * invden[lane] + bias[j];
    gdc_launch();
}

// ---- unified writer: 5 regions in one launch ----
#define NB_A0 12288
#define NB_A1 2048
#define NB_B0 1536
#define NB_B1 512
#define NB_B2 1024
__device__ __forceinline__ void wr_A(const float4* Ab4, const float* scales,
                                     float4* out, int bx, int nI, int ind4, int mode,
                                     int tid) {
    int r = bx & 15;
    int i = (bx >> 4) % nI;
    int b = (bx >> 4) / nI;
    int p = (mode == 0) ? (i/6)*7 + (i%6) : i*7 + 6;
    float s = scales[2*p];
    float4 v = Ab4[(size_t)(b*224 + p)*256 + r*16 + (tid & 15)];
    v.x *= s; v.y *= s; v.z *= s; v.w *= s;
    size_t base = ((size_t)(b*nI + i)*16 + r) * ind4;
    for (int c4 = tid; c4 < ind4; c4 += 256)
        __stcs(&out[base + c4], v);
}
__device__ __forceinline__ void wr_B(const float4* Bb4, const float* scales,
                                     float4* out, int bx, int nI, int cnt, int nSplit,
                                     int mode, int tid) {
    int sp = bx % nSplit;
    int i = (bx / nSplit) % nI;
    int b = (bx / nSplit) / nI;
    int p;
    if (mode == 0)      p = (i/3)*7 + (i%3)*3;
    else if (mode == 1) p = (i/2)*7 + 1 + (i%2);
    else                p = (i/2)*7 + 4 + (i%2);
    float s = scales[2*p + 1];
    float4 v = Bb4[(size_t)(b*224 + p)*256 + tid];
    v.x *= s; v.y *= s; v.z *= s; v.w *= s;
    size_t base = (size_t)(b*nI + i) * ((size_t)cnt * nSplit) + (size_t)sp * cnt;
    for (int f = tid; f < cnt; f += 256)
        __stcs(&out[base + f], v);
}
__global__ __launch_bounds__(256) void write_all(
        const float4* __restrict__ Ab4, const float4* __restrict__ Bb4,
        const float* __restrict__ scales, float* __restrict__ outf) {
    int bx = blockIdx.x;
    int tid = threadIdx.x;
    gdc_wait();
    if (bx < NB_A0) { wr_A(Ab4, scales, (float4*)outf, bx, 192, 4096/4, 0, tid); return; }
    bx -= NB_A0;
    if (bx < NB_A1) { wr_A(Ab4, scales, (float4*)(outf + OFF_AINT), bx, 32, 11008/4, 1, tid); return; }
    bx -= NB_A1;
    if (bx < NB_B0) { wr_B(Bb4, scales, (float4*)(outf + OFF_BHID), bx, 96, 4096, 4, 0, tid); return; }
    bx -= NB_B0;
    if (bx < NB_B1) { wr_B(Bb4, scales, (float4*)(outf + OFF_BKV), bx, 64, 2048, 2, 1, tid); return; }
    bx -= NB_B1;
    wr_B(Bb4, scales, (float4*)(outf + OFF_BINT), bx, 64, 11008, 4, 2, tid);
}

// ---------------- host: PDL launch helper ----------------
template<typename F, typename... Args>
static inline void launch_pdl(F f, dim3 g, dim3 b, size_t smem, Args... args) {
    cudaLaunchConfig_t cfg = {};
    cfg.gridDim = g;
    cfg.blockDim = b;
    cfg.dynamicSmemBytes = smem;
    cfg.stream = 0;
    cudaLaunchAttribute attr[1];
    attr[0].id = cudaLaunchAttributeProgrammaticStreamSerialization;
    attr[0].val.programmaticStreamSerializationAllowed = 1;
    cfg.attrs = attr;
    cfg.numAttrs = 1;
    cudaLaunchKernelEx(&cfg, f, args...);
}

// ---------------- launch ----------------
extern "C" void kernel_launch(void* const* d_in, const int* in_sizes, int n_in,
                              void* d_out, int out_size) {
    const int*   ids   = (const int*)d_in[0];
    const int*   amask = (const int*)d_in[1];
    const float* E     = (const float*)d_in[2];
    const float* qkvw  = (const float*)d_in[3];
    const float* qkvb  = (const float*)d_in[4];
    const float* ow    = (const float*)d_in[5];
    const float* ob    = (const float*)d_in[6];
    const float* ln1g  = (const float*)d_in[7];
    const float* ln1b  = (const float*)d_in[8];
    const float* f1w   = (const float*)d_in[9];
    const float* f1b   = (const float*)d_in[10];
    const float* f2w   = (const float*)d_in[11];
    const float* f2b   = (const float*)d_in[12];
    const float* ln2g  = (const float*)d_in[13];
    const float* ln2b  = (const float*)d_in[14];
    const float* projw = (const float*)d_in[15];
    const float* projb = (const float*)d_in[16];
    const float* a1w   = (const float*)d_in[17];
    const float* a1b   = (const float*)d_in[18];
    const float* a2w   = (const float*)d_in[19];
    const float* a2b   = (const float*)d_in[20];
    const float* bw1   = (const float*)d_in[21];
    const float* bb1   = (const float*)d_in[22];
    const float* bw2   = (const float*)d_in[23];
    const float* bb2   = (const float*)d_in[24];
    const float* scales= (const float*)d_in[25];

    cudaFuncSetAttribute(attn_fused, cudaFuncAttributeMaxDynamicSharedMemorySize, ATT_SMEM);

    float* S = nullptr;
    cudaGetSymbolAddress((void**)&S, g_scratch);
    float* x     = S + S_X;
    float* qkv   = S + S_QKV;
    float* attn  = S + S_ATTN;
    float* ff1   = S + S_FF1;
    float* pool  = S + S_POOL;
    float* pe    = S + S_PE;
    float* dechA = S + S_DECHA;
    float* dechB = S + S_DECHB;
    float* Ab    = S + S_AB;
    float* Bb    = S + S_BB;
    float* part  = S + S_PART;
    float* out   = (float*)d_out;
    const float* FNUL = nullptr;
    float* NUL = nullptr;
    const int* INUL = nullptr;

    for (int l = 0; l < 3; ++l) {
        const int*   gq = (l == 0) ? ids : INUL;
        const float* ge = (l == 0) ? E   : FNUL;
        launch_pdl(gemm32<0,0>, dim3(24, 16, 1), dim3(128), 0,
                   (const float*)x, qkvw + (size_t)l*768*256, qkvb + l*768,
                   qkv, NUL, FNUL, FNUL, FNUL, NUL, gq, ge, TOK, 768, 256);
        launch_pdl(attn_fused, dim3(8, 16), dim3(256), (size_t)ATT_SMEM,
                   (const float*)qkv, amask, attn);
        launch_pdl(gemm32<0,0>, dim3(8, 16, 2), dim3(128), 0,
                   (const float*)attn, ow + (size_t)l*256*256, FNUL,
                   NUL, part, FNUL, FNUL, FNUL, NUL, INUL, FNUL, TOK, 256, 256);
        // ln1 of layer 2 also zeroes the pooled buffer (3 PDL stages before pooling)
        launch_pdl(ksplit_ln, dim3(64), dim3(256), 0,
                   (const float*)part, ob + l*256, x, ln1g + l*256, ln1b + l*256, 2,
                   gq, ge, INUL, NUL, (l == 2) ? pool : NUL);
        launch_pdl(gemm32<1,0>, dim3(64, 16, 1), dim3(128), 0,
                   (const float*)x, f1w + (size_t)l*2048*256, f1b + l*2048,
                   ff1, NUL, FNUL, FNUL, FNUL, NUL, INUL, FNUL, TOK, 2048, 256);
        launch_pdl(gemm32<0,0>, dim3(8, 16, 4), dim3(128), 0,
                   (const float*)ff1, f2w + (size_t)l*256*2048, FNUL,
                   NUL, part, FNUL, FNUL, FNUL, NUL, INUL, FNUL, TOK, 256, 2048);
        // ln2 of layer 2 accumulates pooled sums (masked) via atomics
        launch_pdl(ksplit_ln, dim3(64), dim3(256), 0,
                   (const float*)part, f2b + l*256, x, ln2g + l*256, ln2b + l*256, 4,
                   INUL, FNUL, (l == 2) ? amask : INUL, (l == 2) ? pool : NUL, NUL);
    }

    launch_pdl(pe_kernel, dim3(PEROW/8), dim3(256), 0,
               (const float*)pool, amask, projw, projb, pe);

    launch_pdl(gemm32<2,1>, dim3(8, 28, 2), dim3(128), 0,
               (const float*)pe, a1w, a1b, dechA, NUL,
               (const float*)pe, bw1, bb1, dechB, INUL, FNUL, 896, 256, 512);
    launch_pdl(gemm32<0,1>, dim3(32, 28, 2), dim3(128), 0,
               (const float*)dechA, a2w, a2b, Ab, NUL,
               (const float*)dechB, bw2, bb2, Bb, INUL, FNUL, 896, 1024, 256);

    launch_pdl(write_all, dim3(NB_A0 + NB_A1 + NB_B0 + NB_B1 + NB_B2), dim3(256), 0,
               (const float4*)Ab, (const float4*)Bb, scales, out);
}

// round 12
// speedup vs baseline: 1.1840x; 1.1840x over previous
#include <cuda_runtime.h>
#include <cuda_bf16.h>
#include <cstdint>
#include <cstddef>

// ---------------- problem constants ----------------
#define BSZ   4
#define SEQ   128
#define TOK   (BSZ*SEQ)        // 512
#define DM    256
#define FF    2048
#define PP    224
#define PED   512
#define PEROW (PP*PED)         // 114688

// output region sizes (floats)
#define SZ_AHID (4LL*192*16*4096)
#define SZ_AINT (4LL*32*16*11008)
#define SZ_BHID (4LL*96*4096*16)
#define SZ_BKV  (4LL*64*1024*16)
#define OFF_AINT (SZ_AHID)
#define OFF_BHID (SZ_AHID+SZ_AINT)
#define OFF_BKV  (OFF_BHID+SZ_BHID)
#define OFF_BINT (OFF_BKV+SZ_BKV)

// ---------------- scratch ----------------
#define S_X     0
#define S_QKV   (S_X    + TOK*DM)
#define S_ATTN  (S_QKV  + TOK*3*DM)
#define S_FF1   (S_ATTN + TOK*DM)
#define S_POOL  (S_FF1  + TOK*FF)
#define S_PE    (S_POOL + BSZ*DM)
#define S_DECHA (S_PE   + BSZ*PEROW)
#define S_DECHB (S_DECHA + 896*DM)
#define S_AB    (S_DECHB + 896*DM)
#define S_BB    (S_AB   + 896*1024)
#define S_PART  (S_BB   + 896*1024)
#define S_TOTAL (S_PART + 4*TOK*DM)

__device__ float g_scratch[S_TOTAL];

// ---------------- PDL helpers ----------------
__device__ __forceinline__ void gdc_wait()   { asm volatile("griddepcontrol.wait;" ::: "memory"); }
__device__ __forceinline__ void gdc_launch() { asm volatile("griddepcontrol.launch_dependents;" ::: "memory"); }

// ---------------- math helpers ----------------
__device__ __forceinline__ unsigned f2tf(float x) {
    unsigned u; asm("cvt.rna.tf32.f32 %0, %1;" : "=r"(u) : "f"(x)); return u;
}
__device__ __forceinline__ void mma_tf32(float* d, const unsigned* a, const unsigned* b) {
    asm volatile("mma.sync.aligned.m16n8k8.row.col.f32.tf32.tf32.f32 "
        "{%0,%1,%2,%3}, {%4,%5,%6,%7}, {%8,%9}, {%0,%1,%2,%3};\n"
        : "+f"(d[0]), "+f"(d[1]), "+f"(d[2]), "+f"(d[3])
        : "r"(a[0]), "r"(a[1]), "r"(a[2]), "r"(a[3]), "r"(b[0]), "r"(b[1]));
}
__device__ __forceinline__ void cp16(float* smem_dst, const float* gsrc) {
    unsigned s = (unsigned)__cvta_generic_to_shared(smem_dst);
    asm volatile("cp.async.ca.shared.global [%0], [%1], 16;" :: "r"(s), "l"(gsrc));
}
__device__ __forceinline__ void cp_commit() { asm volatile("cp.async.commit_group;"); }
template<int N>
__device__ __forceinline__ void cp_wait() { asm volatile("cp.async.wait_group %0;" :: "n"(N)); }

// ---------------- kernels ----------------

// C[m,n] = epi( sum_k X[m,k]*W[n,k] + bias[n] ), tf32 tensor cores.
// BM=BN=32, BK=32, 128 threads (4 warps, 16x16 warp tile), 4-stage cp.async pipeline.
// W prefetched pre-gdc_wait; gids!=null gathers X rows from Etab[gids[row]].
#define SK 36
#define STG 4
template<int EPI, int BATCH>
__global__ __launch_bounds__(128) void gemm32(
        const float* __restrict__ X, const float* __restrict__ W,
        const float* __restrict__ bias, float* __restrict__ C,
        float* __restrict__ Cpart,
        const float* __restrict__ X2, const float* __restrict__ W2,
        const float* __restrict__ bias2, float* __restrict__ C2,
        const int* __restrict__ gids, const float* __restrict__ Etab,
        int M, int N, int K) {
    __shared__ float Xs[STG][32][SK];
    __shared__ float Ws[STG][32][SK];
    int tid = threadIdx.x;
    int lane = tid & 31, wid = tid >> 5;
    int wm = wid & 1, wn = wid >> 1;
    int r = lane >> 2, cq = lane & 3;
    int m0 = blockIdx.y * 32, n0 = blockIdx.x * 32;
    int kbeg, nk;
    if (BATCH) {
        if (blockIdx.z) { X = X2; W = W2; bias = bias2; C = C2; }
        kbeg = 0; nk = K >> 5;
    } else {
        int kchunk = K / gridDim.z;
        kbeg = blockIdx.z * kchunk;
        nk = kchunk >> 5;
    }

    int row2 = tid >> 3;              // 0..15
    int colq = (tid & 7) * 4;         // 0..28
    size_t rstep = (size_t)16 * K;
    const float *xrow0, *xrow1;
    if (gids) {
        xrow0 = Etab + (size_t)gids[m0 + row2] * 256 + colq;
        xrow1 = Etab + (size_t)gids[m0 + row2 + 16] * 256 + colq;
    } else {
        xrow0 = X + (size_t)(m0 + row2) * K + kbeg + colq;
        xrow1 = xrow0 + rstep;
    }
    const float* wg = W + (size_t)(n0 + row2) * K + kbeg + colq;

    #pragma unroll
    for (int s = 0; s < STG-1; ++s) {
        if (s < nk) {
            const float* wp = wg + s*32;
            cp16(&Ws[s][row2][colq],    wp);
            cp16(&Ws[s][row2+16][colq], wp + rstep);
        }
    }
    cp_commit();                       // G0 (weights, pre-wait)

    gdc_wait();

    #pragma unroll
    for (int s = 0; s < STG-1; ++s) {  // G1..G3 = X stages
        if (s < nk) {
            cp16(&Xs[s][row2][colq],    xrow0 + s*32);
            cp16(&Xs[s][row2+16][colq], xrow1 + s*32);
        }
        cp_commit();
    }

    float acc[2][4] = {};

    for (int kt = 0; kt < nk; ++kt) {
        int buf = kt & (STG-1);
        cp_wait<STG-2>();
        __syncthreads();
        {
            int ks2 = kt + STG - 1;
            if (ks2 < nk) {
                int b2 = ks2 & (STG-1);
                cp16(&Xs[b2][row2][colq],    xrow0 + ks2*32);
                cp16(&Xs[b2][row2+16][colq], xrow1 + ks2*32);
                const float* wp = wg + ks2*32;
                cp16(&Ws[b2][row2][colq],    wp);
                cp16(&Ws[b2][row2+16][colq], wp + rstep);
            }
            cp_commit();
        }
        #pragma unroll
        for (int ks = 0; ks < 4; ++ks) {
            unsigned af[4];
            int mr = wm*16 + r;
            af[0] = f2tf(Xs[buf][mr][ks*8 + cq]);
            af[1] = f2tf(Xs[buf][mr + 8][ks*8 + cq]);
            af[2] = f2tf(Xs[buf][mr][ks*8 + cq + 4]);
            af[3] = f2tf(Xs[buf][mr + 8][ks*8 + cq + 4]);
            #pragma unroll
            for (int nt = 0; nt < 2; ++nt) {
                unsigned bf[2];
                int nr = wn*16 + nt*8 + r;
                bf[0] = f2tf(Ws[buf][nr][ks*8 + cq]);
                bf[1] = f2tf(Ws[buf][nr][ks*8 + cq + 4]);
                mma_tf32(acc[nt], af, bf);
            }
        }
    }

    int m = m0 + wm*16 + r;
    if (!BATCH && gridDim.z > 1) {
        float* P = Cpart + (size_t)blockIdx.z * M * N;
        #pragma unroll
        for (int nt = 0; nt < 2; ++nt) {
            int n = n0 + wn*16 + nt*8 + cq*2;
            #pragma unroll
            for (int half = 0; half < 2; ++half)
                *reinterpret_cast<float2*>(&P[(size_t)(m + half*8)*N + n]) =
                    make_float2(acc[nt][half*2], acc[nt][half*2+1]);
        }
    } else {
        #pragma unroll
        for (int nt = 0; nt < 2; ++nt) {
            int n = n0 + wn*16 + nt*8 + cq*2;
            #pragma unroll
            for (int half = 0; half < 2; ++half) {
                float v0 = acc[nt][half*2+0] + bias[n];
                float v1 = acc[nt][half*2+1] + bias[n+1];
                if (EPI == 1) { v0 = fmaxf(v0, 0.f); v1 = fmaxf(v1, 0.f); }
                if (EPI == 2) {
                    v0 = 0.5f*v0*(1.f + erff(v0*0.70710678118654752f));
                    v1 = 0.5f*v1*(1.f + erff(v1*0.70710678118654752f));
                }
                *reinterpret_cast<float2*>(&C[(size_t)(m + half*8)*N + n]) = make_float2(v0, v1);
            }
        }
    }
    gdc_launch();
}

// split-K reduce + bias + residual + LayerNorm; block-per-row (512 blocks x 256 thr),
// warp-shuffle reduction (2 block barriers total).
// gids!=null: residual gathered from Etab[gids[row]] (layer-0 fold).
__global__ void ksplit_ln(const float* __restrict__ P, const float* __restrict__ bias,
                          float* __restrict__ x, const float* __restrict__ g,
                          const float* __restrict__ b, int parts,
                          const int* __restrict__ gids, const float* __restrict__ Etab) {
    int row = blockIdx.x, d = threadIdx.x;
    int lane = d & 31, wrp = d >> 5;
    __shared__ float ws1[8], ws2[8];
    size_t idx = (size_t)row*256 + d;
    const float* rsrc = gids ? (Etab + (size_t)gids[row]*256 + d) : nullptr;
    gdc_wait();
    float s = bias[d];
    for (int p = 0; p < parts; ++p) s += P[(size_t)p*TOK*DM + idx];
    float resid = gids ? *rsrc : x[idx];
    float h = resid + s;
    float s1 = h, s2 = h*h;
    #pragma unroll
    for (int off = 16; off > 0; off >>= 1) {
        s1 += __shfl_xor_sync(0xFFFFFFFFu, s1, off);
        s2 += __shfl_xor_sync(0xFFFFFFFFu, s2, off);
    }
    if (lane == 0) { ws1[wrp] = s1; ws2[wrp] = s2; }
    __syncthreads();
    if (wrp == 0) {
        float a1 = (lane < 8) ? ws1[lane] : 0.f;
        float a2 = (lane < 8) ? ws2[lane] : 0.f;
        #pragma unroll
        for (int off = 4; off > 0; off >>= 1) {
            a1 += __shfl_xor_sync(0xFFFFFFFFu, a1, off);
            a2 += __shfl_xor_sync(0xFFFFFFFFu, a2, off);
        }
        if (lane == 0) { ws1[0] = a1; ws2[0] = a2; }
    }
    __syncthreads();
    float m = ws1[0] * (1.f/256.f);
    float var = ws2[0] * (1.f/256.f) - m*m;
    x[idx] = (h - m) * rsqrtf(var + 1e-5f) * g[d] + b[d];
    gdc_launch();
}

// Fused attention: block = (q-chunk of 16, b*4+h). 256 threads, grid (8,16).
#define AQ_OFF 0
#define AK_OFF (16*68)
#define AV_OFF (AK_OFF + 128*68)
#define AP_OFF (AV_OFF + 128*68)
#define ATT_SMEM ((AP_OFF + 16*129)*4)
__global__ void attn_fused(const float* __restrict__ qkv, const int* __restrict__ mask,
                           float* __restrict__ o) {
    extern __shared__ float sm[];
    int tid = threadIdx.x;
    int qc = blockIdx.x;
    int bh = blockIdx.y;
    int b = bh >> 2, h = bh & 3;

    gdc_wait();
    const float4* src = reinterpret_cast<const float4*>(qkv);
    {
        int row = tid >> 4, d4 = tid & 15;
        float4 v = src[((size_t)(b*128 + qc*16 + row)*768 + h*64) / 4 + d4];
        *reinterpret_cast<float4*>(&sm[AQ_OFF + row*68 + d4*4]) = v;
    }
    #pragma unroll
    for (int it = 0; it < 8; ++it) {
        int e = it*256 + tid;
        int row = e >> 4, d4 = e & 15;
        float4 k = src[((size_t)(b*128 + row)*768 + 256 + h*64) / 4 + d4];
        float4 v = src[((size_t)(b*128 + row)*768 + 512 + h*64) / 4 + d4];
        *reinterpret_cast<float4*>(&sm[AK_OFF + row*68 + d4*4]) = k;
        *reinterpret_cast<float4*>(&sm[AV_OFF + row*68 + d4*4]) = v;
    }
    __syncthreads();

    int q = tid >> 4;
    int kb = tid & 15;
    float s[8];
    #pragma unroll
    for (int i = 0; i < 8; ++i) {
        int k = kb + 16*i;
        const float4* qp = reinterpret_cast<const float4*>(&sm[AQ_OFF + q*68]);
        const float4* kp = reinterpret_cast<const float4*>(&sm[AK_OFF + k*68]);
        float acc = 0.f;
        #pragma unroll
        for (int d4 = 0; d4 < 16; ++d4) {
            float4 a = qp[d4], c = kp[d4];
            acc += a.x*c.x + a.y*c.y + a.z*c.z + a.w*c.w;
        }
        acc *= 0.125f;
        if (mask[b*128 + k] == 0) acc = -1e9f;
        s[i] = acc;
    }
    float mx = s[0];
    #pragma unroll
    for (int i = 1; i < 8; ++i) mx = fmaxf(mx, s[i]);
    #pragma unroll
    for (int off = 1; off < 16; off <<= 1)
        mx = fmaxf(mx, __shfl_xor_sync(0xFFFFFFFFu, mx, off));
    float sum = 0.f;
    #pragma unroll
    for (int i = 0; i < 8; ++i) { s[i] = __expf(s[i] - mx); sum += s[i]; }
    #pragma unroll
    for (int off = 1; off < 16; off <<= 1)
        sum += __shfl_xor_sync(0xFFFFFFFFu, sum, off);
    float inv = 1.f / sum;
    #pragma unroll
    for (int i = 0; i < 8; ++i)
        sm[AP_OFF + q*129 + kb + 16*i] = s[i] * inv;
    __syncthreads();

    int dg = tid & 15;
    float4 acc4 = {0.f, 0.f, 0.f, 0.f};
    const float* Pr = &sm[AP_OFF + q*129];
    #pragma unroll 4
    for (int k = 0; k < 128; ++k) {
        float p = Pr[k];
        float4 v = *reinterpret_cast<const float4*>(&sm[AV_OFF + k*68 + dg*4]);
        acc4.x += p*v.x; acc4.y += p*v.y; acc4.z += p*v.z; acc4.w += p*v.w;
    }
    size_t orow = (size_t)(b*128 + qc*16 + q)*256 + h*64 + dg*4;
    *reinterpret_cast<float4*>(&o[orow]) = acc4;
    gdc_launch();
}

// pool: grid 4, block 1024 (4 token-groups x 256 dims), 2-level reduce
__global__ __launch_bounds__(1024) void pool_kernel(
        const float* __restrict__ x, const int* __restrict__ mask,
        float* __restrict__ pooled) {
    __shared__ float red[1024];
    __shared__ float redden[1024];
    int b = blockIdx.x;
    int tid = threadIdx.x;
    int d = tid & 255, tg = tid >> 8;
    gdc_wait();
    float s = 0.f, den = 0.f;
    #pragma unroll 8
    for (int t = tg*32; t < tg*32 + 32; ++t) {
        float am = (float)mask[b*128 + t];
        s += x[(size_t)(b*128 + t)*256 + d] * am;
        den += am;
    }
    red[tid] = s; redden[tid] = den;
    __syncthreads();
    if (tg == 0) {
        s   = red[d] + red[d+256] + red[d+512] + red[d+768];
        den = redden[d] + redden[d+256] + redden[d+512] + redden[d+768];
        pooled[b*256 + d] = s / fmaxf(den, 1.0f);
    }
    gdc_launch();
}

__global__ void pe_kernel(const float* __restrict__ pooled, const float* __restrict__ W,
                          const float* __restrict__ bias, float* __restrict__ pe) {
    __shared__ float sp[1024];
    int t = threadIdx.x;
    int warp = t >> 5, lane = t & 31;
    int j = blockIdx.x * 8 + warp;
    const float4* w4 = reinterpret_cast<const float4*>(W + (size_t)j * 256);
    float4 w0 = w4[lane];
    float4 w1 = w4[lane + 32];
    gdc_wait();
    #pragma unroll
    for (int i = 0; i < 4; ++i) sp[t + i*256] = pooled[t + i*256];
    __syncthreads();
    int k0 = lane * 4, k1 = (lane + 32) * 4;
    float acc[4];
    #pragma unroll
    for (int b = 0; b < 4; ++b) {
        const float* p = &sp[b*256];
        acc[b] = w0.x*p[k0] + w0.y*p[k0+1] + w0.z*p[k0+2] + w0.w*p[k0+3]
               + w1.x*p[k1] + w1.y*p[k1+1] + w1.z*p[k1+2] + w1.w*p[k1+3];
    }
    #pragma unroll
    for (int b = 0; b < 4; ++b)
        #pragma unroll
        for (int off = 16; off > 0; off >>= 1)
            acc[b] += __shfl_xor_sync(0xFFFFFFFFu, acc[b], off);
    if (lane < 4) pe[(size_t)lane * PEROW + j] = acc[lane] + bias[j];
    gdc_launch();
}

// ---- unified writer: 5 regions in one launch ----
#define NB_A0 12288
#define NB_A1 2048
#define NB_B0 1536
#define NB_B1 512
#define NB_B2 1024
__device__ __forceinline__ void wr_A(const float4* Ab4, const float* scales,
                                     float4* out, int bx, int nI, int ind4, int mode,
                                     int tid) {
    int r = bx & 15;
    int i = (bx >> 4) % nI;
    int b = (bx >> 4) / nI;
    int p = (mode == 0) ? (i/6)*7 + (i%6) : i*7 + 6;
    float s = scales[2*p];
    float4 v = Ab4[(size_t)(b*224 + p)*256 + r*16 + (tid & 15)];
    v.x *= s; v.y *= s; v.z *= s; v.w *= s;
    size_t base = ((size_t)(b*nI + i)*16 + r) * ind4;
    for (int c4 = tid; c4 < ind4; c4 += 256)
        __stcs(&out[base + c4], v);
}
__device__ __forceinline__ void wr_B(const float4* Bb4, const float* scales,
                                     float4* out, int bx, int nI, int cnt, int nSplit,
                                     int mode, int tid) {
    int sp = bx % nSplit;
    int i = (bx / nSplit) % nI;
    int b = (bx / nSplit) / nI;
    int p;
    if (mode == 0)      p = (i/3)*7 + (i%3)*3;
    else if (mode == 1) p = (i/2)*7 + 1 + (i%2);
    else                p = (i/2)*7 + 4 + (i%2);
    float s = scales[2*p + 1];
    float4 v = Bb4[(size_t)(b*224 + p)*256 + tid];
    v.x *= s; v.y *= s; v.z *= s; v.w *= s;
    size_t base = (size_t)(b*nI + i) * ((size_t)cnt * nSplit) + (size_t)sp * cnt;
    for (int f = tid; f < cnt; f += 256)
        __stcs(&out[base + f], v);
}
__global__ __launch_bounds__(256) void write_all(
        const float4* __restrict__ Ab4, const float4* __restrict__ Bb4,
        const float* __restrict__ scales, float* __restrict__ outf) {
    int bx = blockIdx.x;
    int tid = threadIdx.x;
    gdc_wait();
    if (bx < NB_A0) { wr_A(Ab4, scales, (float4*)outf, bx, 192, 4096/4, 0, tid); return; }
    bx -= NB_A0;
    if (bx < NB_A1) { wr_A(Ab4, scales, (float4*)(outf + OFF_AINT), bx, 32, 11008/4, 1, tid); return; }
    bx -= NB_A1;
    if (bx < NB_B0) { wr_B(Bb4, scales, (float4*)(outf + OFF_BHID), bx, 96, 4096, 4, 0, tid); return; }
    bx -= NB_B0;
    if (bx < NB_B1) { wr_B(Bb4, scales, (float4*)(outf + OFF_BKV), bx, 64, 2048, 2, 1, tid); return; }
    bx -= NB_B1;
    wr_B(Bb4, scales, (float4*)(outf + OFF_BINT), bx, 64, 11008, 4, 2, tid);
}

// ---------------- host: PDL launch helper ----------------
template<typename F, typename... Args>
static inline void launch_pdl(F f, dim3 g, dim3 b, size_t smem, Args... args) {
    cudaLaunchConfig_t cfg = {};
    cfg.gridDim = g;
    cfg.blockDim = b;
    cfg.dynamicSmemBytes = smem;
    cfg.stream = 0;
    cudaLaunchAttribute attr[1];
    attr[0].id = cudaLaunchAttributeProgrammaticStreamSerialization;
    attr[0].val.programmaticStreamSerializationAllowed = 1;
    cfg.attrs = attr;
    cfg.numAttrs = 1;
    cudaLaunchKernelEx(&cfg, f, args...);
}

// ---------------- launch ----------------
extern "C" void kernel_launch(void* const* d_in, const int* in_sizes, int n_in,
                              void* d_out, int out_size) {
    const int*   ids   = (const int*)d_in[0];
    const int*   amask = (const int*)d_in[1];
    const float* E     = (const float*)d_in[2];
    const float* qkvw  = (const float*)d_in[3];
    const float* qkvb  = (const float*)d_in[4];
    const float* ow    = (const float*)d_in[5];
    const float* ob    = (const float*)d_in[6];
    const float* ln1g  = (const float*)d_in[7];
    const float* ln1b  = (const float*)d_in[8];
    const float* f1w   = (const float*)d_in[9];
    const float* f1b   = (const float*)d_in[10];
    const float* f2w   = (const float*)d_in[11];
    const float* f2b   = (const float*)d_in[12];
    const float* ln2g  = (const float*)d_in[13];
    const float* ln2b  = (const float*)d_in[14];
    const float* projw = (const float*)d_in[15];
    const float* projb = (const float*)d_in[16];
    const float* a1w   = (const float*)d_in[17];
    const float* a1b   = (const float*)d_in[18];
    const float* a2w   = (const float*)d_in[19];
    const float* a2b   = (const float*)d_in[20];
    const float* bw1   = (const float*)d_in[21];
    const float* bb1   = (const float*)d_in[22];
    const float* bw2   = (const float*)d_in[23];
    const float* bb2   = (const float*)d_in[24];
    const float* scales= (const float*)d_in[25];

    cudaFuncSetAttribute(attn_fused, cudaFuncAttributeMaxDynamicSharedMemorySize, ATT_SMEM);

    float* S = nullptr;
    cudaGetSymbolAddress((void**)&S, g_scratch);
    float* x     = S + S_X;
    float* qkv   = S + S_QKV;
    float* attn  = S + S_ATTN;
    float* ff1   = S + S_FF1;
    float* pool  = S + S_POOL;
    float* pe    = S + S_PE;
    float* dechA = S + S_DECHA;
    float* dechB = S + S_DECHB;
    float* Ab    = S + S_AB;
    float* Bb    = S + S_BB;
    float* part  = S + S_PART;
    float* out   = (float*)d_out;
    const float* FNUL = nullptr;
    float* NUL = nullptr;
    const int* INUL = nullptr;

    for (int l = 0; l < 3; ++l) {
        const int*   gq = (l == 0) ? ids : INUL;
        const float* ge = (l == 0) ? E   : FNUL;
        launch_pdl(gemm32<0,0>, dim3(24, 16, 1), dim3(128), 0,
                   (const float*)x, qkvw + (size_t)l*768*256, qkvb + l*768,
                   qkv, NUL, FNUL, FNUL, FNUL, NUL, gq, ge, TOK, 768, 256);
        launch_pdl(attn_fused, dim3(8, 16), dim3(256), (size_t)ATT_SMEM,
                   (const float*)qkv, amask, attn);
        launch_pdl(gemm32<0,0>, dim3(8, 16, 2), dim3(128), 0,
                   (const float*)attn, ow + (size_t)l*256*256, FNUL,
                   NUL, part, FNUL, FNUL, FNUL, NUL, INUL, FNUL, TOK, 256, 256);
        launch_pdl(ksplit_ln, dim3(TOK), dim3(256), 0,
                   (const float*)part, ob + l*256, x, ln1g + l*256, ln1b + l*256, 2,
                   gq, ge);
        launch_pdl(gemm32<1,0>, dim3(64, 16, 1), dim3(128), 0,
                   (const float*)x, f1w + (size_t)l*2048*256, f1b + l*2048,
                   ff1, NUL, FNUL, FNUL, FNUL, NUL, INUL, FNUL, TOK, 2048, 256);
        launch_pdl(gemm32<0,0>, dim3(8, 16, 4), dim3(128), 0,
                   (const float*)ff1, f2w + (size_t)l*256*2048, FNUL,
                   NUL, part, FNUL, FNUL, FNUL, NUL, INUL, FNUL, TOK, 256, 2048);
        launch_pdl(ksplit_ln, dim3(TOK), dim3(256), 0,
                   (const float*)part, f2b + l*256, x, ln2g + l*256, ln2b + l*256, 4,
                   INUL, FNUL);
    }

    launch_pdl(pool_kernel, dim3(BSZ), dim3(1024), 0, (const float*)x, amask, pool);
    launch_pdl(pe_kernel, dim3(PEROW/8), dim3(256), 0,
               (const float*)pool, projw, projb, pe);

    launch_pdl(gemm32<2,1>, dim3(8, 28, 2), dim3(128), 0,
               (const float*)pe, a1w, a1b, dechA, NUL,
               (const float*)pe, bw1, bb1, dechB, INUL, FNUL, 896, 256, 512);
    launch_pdl(gemm32<0,1>, dim3(32, 28, 2), dim3(128), 0,
               (const float*)dechA, a2w, a2b, Ab, NUL,
               (const float*)dechB, bw2, bb2, Bb, INUL, FNUL, 896, 1024, 256);

    launch_pdl(write_all, dim3(NB_A0 + NB_A1 + NB_B0 + NB_B1 + NB_B2), dim3(256), 0,
               (const float4*)Ab, (const float4*)Bb, scales, out);
}